// round 14
// baseline (speedup 1.0000x reference)
#include <cuda_runtime.h>
#include <cuda_fp16.h>
#include <math.h>
#include <cstdint>

#define Hh 96
#define Ww 128
#define HP 104
#define WP 136
#define CIN 128
#define COUT 128
#define NB 2
#define NBR 6
#define EXH 146            // HP + 2*21
#define EXW 178            // WP + 2*21
#define EXHW (EXH*EXW)

// -------- scratch (device globals: allocation-free) --------
__device__ __align__(16) __half g_ygh[(size_t)NBR * NB * HP * WP * 128];   // conv out [br][bb][row][col][ch]
__device__ __align__(16) float g_yn[(size_t)NBR * NB * 4 * HP * WP];
__device__ __align__(16) float g_xn[(size_t)NB * 4 * Hh * Ww];
__device__ __align__(16) __half g_xh[(size_t)NB * Hh * Ww * 128];          // x fp16 [bb][row][col][ch]
__device__ __align__(16) __half2 g_yext2[(size_t)NB * 64 * EXHW + 64];     // ci-pair fp16
__device__ __align__(16) __half g_wAh[(size_t)NBR * 9 * COUT * CIN];       // fp16 weights [br][tap][co][ci]

__constant__ int c_rad[6] = {1, 3, 5, 9, 13, 21};

__device__ __forceinline__ void mma16(float* c, const uint32_t* a, uint32_t b0, uint32_t b1) {
    asm volatile(
        "mma.sync.aligned.m16n8k16.row.col.f32.f16.f16.f32 "
        "{%0,%1,%2,%3}, {%4,%5,%6,%7}, {%8,%9}, {%0,%1,%2,%3};"
        : "+f"(c[0]), "+f"(c[1]), "+f"(c[2]), "+f"(c[3])
        : "r"(a[0]), "r"(a[1]), "r"(a[2]), "r"(a[3]), "r"(b0), "r"(b1));
}
__device__ __forceinline__ void ldsm_x4(uint32_t* r, uint32_t addr) {
    asm volatile("ldmatrix.sync.aligned.m8n8.x4.shared.b16 {%0,%1,%2,%3}, [%4];"
                 : "=r"(r[0]), "=r"(r[1]), "=r"(r[2]), "=r"(r[3]) : "r"(addr));
}
__device__ __forceinline__ void ldsm_x2(uint32_t* r, uint32_t addr) {
    asm volatile("ldmatrix.sync.aligned.m8n8.x2.shared.b16 {%0,%1}, [%2];"
                 : "=r"(r[0]), "=r"(r[1]) : "r"(addr));
}
__device__ __forceinline__ void cpa16(void* dst, const void* src) {
    uint32_t d = (uint32_t)__cvta_generic_to_shared(dst);
    asm volatile("cp.async.cg.shared.global [%0], [%1], 16;" :: "r"(d), "l"(src));
}
__device__ __forceinline__ void cpa4(void* dst, const void* src) {
    uint32_t d = (uint32_t)__cvta_generic_to_shared(dst);
    asm volatile("cp.async.ca.shared.global [%0], [%1], 4;" :: "r"(d), "l"(src));
}
#define CP_COMMIT() asm volatile("cp.async.commit_group;" ::: "memory")
#define CP_WAIT0()  asm volatile("cp.async.wait_group 0;" ::: "memory")

// ---------------- y_ext fp16 half2 (ci pairs): reflect pad + 21 zero halo ----------------
// grid: (1, EXH, NB*64), block 192 -> div-free index math
__global__ void pad_kernel(const float* __restrict__ y) {
    int c = threadIdx.x;
    if (c >= EXW) return;
    int rr = blockIdx.y;
    int cp = blockIdx.z & 63, bb = blockIdx.z >> 6;
    int pr = rr - 21, pc = c - 21;
    float v0 = 0.f, v1 = 0.f;
    if (pr >= 0 && pr < HP && pc >= 0 && pc < WP) {
        int yr = pr - 4; yr = yr < 0 ? -yr : yr; yr = yr >= Hh ? 2 * Hh - 2 - yr : yr;
        int yc = pc - 4; yc = yc < 0 ? -yc : yc; yc = yc >= Ww ? 2 * Ww - 2 - yc : yc;
        const float* p = y + ((size_t)bb * CIN + 2 * cp) * (Hh * Ww) + (size_t)yr * Ww + yc;
        v0 = p[0]; v1 = p[Hh * Ww];
    }
    g_yext2[((size_t)(bb * 64 + cp) * EXH + rr) * EXW + c] = __floats2half2_rn(v0, v1);
}

// ---------------- weight transform: wAh[br][tap][co][ci] fp16 ----------------
__global__ void wt_kernel(const float* __restrict__ w) {
    int idx = blockIdx.x * blockDim.x + threadIdx.x;
    if (idx >= NBR * 9 * COUT * CIN) return;
    int ci = idx % CIN; int t = idx / CIN;
    int co = t % COUT; t /= COUT;
    int tap = t % 9; int br = t / 9;
    g_wAh[idx] = __float2half_rn(w[(((size_t)br * COUT + co) * CIN + ci) * 9 + tap]);
}

// ---------------- xn + x fp16 transpose ----------------
// grid: (48, NB*4), block 256 -> div-free
__global__ void xn_kernel(const float* __restrict__ x) {
    int hw = blockIdx.x * 256 + threadIdx.x;
    int g = blockIdx.y & 3, bb = blockIdx.y >> 2;
    const float* xp = x + ((size_t)bb * CIN + g * 32) * (Hh * Ww) + hw;
    __half* xo = g_xh + ((size_t)bb * Hh * Ww + hw) * 128 + g * 32;
    float s = 0.f;
#pragma unroll
    for (int c = 0; c < 32; c++) {
        float v = xp[(size_t)c * Hh * Ww];
        s += v * v;
        xo[c] = __float2half_rn(v);
    }
    g_xn[((size_t)bb * 4 + g) * Hh * Ww + hw] = sqrtf(s);
}

// ---------------- fp16 mma.sync conv, K=64 per stage ----------------
#define LDA2 72
#define BCOL 36
#define A_HALFS 9216                 // 128*72
#define B_H2 6408                    // 178*36
#define OFF_B 36864                  // bytes: 2 A stages
#define CONV_SMEM (36864 + 2 * (B_H2 * 4))   // 88128 B

__device__ __forceinline__ void stage_A(__half* Abase, int it, int tid, const __half* wbr) {
    int qp = it / 9, tap = it % 9;
    const __half* wsrc = wbr + (size_t)tap * COUT * CIN + qp * 64;
#pragma unroll
    for (int i = tid; i < 1024; i += 256) {
        int co = i >> 3, k8 = i & 7;
        cpa16(Abase + co * LDA2 + k8 * 8, wsrc + (size_t)co * CIN + k8 * 8);
    }
}

// stage piece of B stage s = qp*3+kh. Div-free: thread t -> kr = t>>3, c = (t&7)+8j.
__device__ __forceinline__ void stage_B(__half2* bt, int s, int piece, int tid,
                                        const __half2* yb2, int r, int d) {
    int qp = s / 3, kh = s % 3;
    int kr = tid >> 3, c0 = tid & 7;
    const __half2* rowp = yb2 + (size_t)(qp * 32 + kr) * EXHW
                        + (size_t)(r + 21 + d * (kh - 1)) * EXW;
    __half2* dst = bt + kr;
    if (piece < 2) {
        int jlo = piece * 8;
#pragma unroll
        for (int j = 0; j < 8; j++) {
            int c = c0 + 8 * (jlo + j);
            cpa4(dst + c * BCOL, rowp + c);
        }
    } else {
#pragma unroll
        for (int j = 16; j < 23; j++) {
            int c = c0 + 8 * j;
            if (c < EXW) cpa4(dst + c * BCOL, rowp + c);
        }
    }
}

__global__ __launch_bounds__(256, 2) void conv_mma_kernel(const float* __restrict__ bias) {
    extern __shared__ __align__(16) char dsm[];
    __half* Asm = (__half*)dsm;
    __half2* Bsm = (__half2*)(dsm + OFF_B);
    __half* ep = (__half*)dsm;     // epilogue reuse

    int tid = threadIdx.x, warp = tid >> 5, lane = tid & 31;
    int gq = lane >> 2, tig = lane & 3;
    int br = blockIdx.y >> 1, bb = blockIdx.y & 1;
    int r = blockIdx.x;
    int d = c_rad[br];
    int wm = warp & 3, wn = warp >> 2;
    int ntiles = wn ? 8 : 9;
    int tbase = wn * 9;

    const __half* wbr = g_wAh + (size_t)br * 9 * COUT * CIN;
    const __half2* yb2 = g_yext2 + (size_t)bb * 64 * EXHW;

    int aro = (lane & 15);
    int ako = (lane >> 4) << 3;
    int bco = (lane & 7) + ((lane >> 4) & 1) * 8;
    int bko = ((lane >> 3) & 1) * 4;
    int kkbase = wn * 2 + wm;      // warp-staggered kk2 start (convoy break)

    float acc[2][9][4];
#pragma unroll
    for (int mt = 0; mt < 2; mt++)
#pragma unroll
        for (int t = 0; t < 9; t++)
#pragma unroll
            for (int u = 0; u < 4; u++) acc[mt][t][u] = 0.f;

    // prestage: full B stage 0 + A0, group 0
    stage_B(Bsm, 0, 0, tid, yb2, r, d);
    stage_B(Bsm, 0, 1, tid, yb2, r, d);
    stage_B(Bsm, 0, 2, tid, yb2, r, d);
    stage_A(Asm, 0, tid, wbr);
    CP_COMMIT();

    for (int it = 0; it < 18; ++it) {
        int s = it / 3, p = it % 3;
        int kw = p;
        CP_WAIT0();
        __syncthreads();

        uint32_t sAb = (uint32_t)__cvta_generic_to_shared(Asm + (it & 1) * A_HALFS);
        uint32_t sBb = (uint32_t)__cvta_generic_to_shared(Bsm + (s & 1) * B_H2);
        int off = 21 + d * (kw - 1);

        auto kk2_block = [&](int kk2) {
            uint32_t a0[4], a1[4];
            ldsm_x4(a0, sAb + ((wm * 32 + aro) * LDA2 + kk2 * 16 + ako) * 2);
            ldsm_x4(a1, sAb + ((wm * 32 + 16 + aro) * LDA2 + kk2 * 16 + ako) * 2);
#pragma unroll
            for (int tq = 0; tq < 4; tq++) {
                int tp = (tq + wm) & 3;                     // rotate tile order per wm
                uint32_t b[4];
                int colb = off + (tbase + 2 * tp) * 8 + bco;
                ldsm_x4(b, sBb + (colb * BCOL + kk2 * 8 + bko) * 4);
                mma16(acc[0][2 * tp], a0, b[0], b[1]);
                mma16(acc[1][2 * tp], a1, b[0], b[1]);
                mma16(acc[0][2 * tp + 1], a0, b[2], b[3]);
                mma16(acc[1][2 * tp + 1], a1, b[2], b[3]);
            }
            if (ntiles == 9) {
                uint32_t b[2];
                int colb = off + (tbase + 8) * 8 + bco;
                ldsm_x2(b, sBb + (colb * BCOL + kk2 * 8 + bko) * 4);
                mma16(acc[0][8], a0, b[0], b[1]);
                mma16(acc[1][8], a1, b[0], b[1]);
            }
        };

        kk2_block(kkbase & 3);
        // stage next (hidden under remaining tensor work)
        if (s + 1 < 6) stage_B(Bsm + ((s + 1) & 1) * B_H2, s + 1, p, tid, yb2, r, d);
        if (it + 1 < 18) stage_A(Asm + ((it + 1) & 1) * A_HALFS, it + 1, tid, wbr);
        CP_COMMIT();
        kk2_block((kkbase + 1) & 3);
        kk2_block((kkbase + 2) & 3);
        kk2_block((kkbase + 3) & 3);
    }
    CP_WAIT0();
    __syncthreads();

    // epilogue: bias + fp16 transpose -> g_ygh[row][col][ch]
#pragma unroll
    for (int mt = 0; mt < 2; mt++) {
        int co0 = wm * 32 + mt * 16 + gq, co1 = co0 + 8;
        float bv0 = bias[br * COUT + co0], bv1 = bias[br * COUT + co1];
#pragma unroll
        for (int t = 0; t < 9; t++) {
            if (t < ntiles) {
                int col = (tbase + t) * 8 + 2 * tig;
                ep[col * 128 + co0] = __float2half(acc[mt][t][0] + bv0);
                ep[(col + 1) * 128 + co0] = __float2half(acc[mt][t][1] + bv0);
                ep[col * 128 + co1] = __float2half(acc[mt][t][2] + bv1);
                ep[(col + 1) * 128 + co1] = __float2half(acc[mt][t][3] + bv1);
            }
        }
    }
    __syncthreads();
    __half* dst = g_ygh + ((size_t)(br * NB + bb) * HP + r) * WP * 128;
    const uint4* src = (const uint4*)ep;
    for (int i = tid; i < 136 * 128 / 8; i += 256)
        ((uint4*)dst)[i] = src[i];

    // fused yn: 136 px x 4 groups from the row already in smem
    for (int i = tid; i < 544; i += 256) {
        int col = i >> 2, g = i & 3;
        const __half2* pp = (const __half2*)(ep + col * 128 + g * 32);
        float s = 0.f;
#pragma unroll
        for (int k = 0; k < 16; k++) {
            int kk = (k + col) & 15;
            float2 f = __half22float2(pp[kk]);
            s += f.x * f.x + f.y * f.y;
        }
        g_yn[(((size_t)br * NB + bb) * 4 + g) * HP * WP + (size_t)r * WP + col] = sqrtf(s);
    }
}

// ---------------- tensor-core 81-shift correlation ----------------
#define YLD 40

__global__ __launch_bounds__(256, 3) void corr_kernel(float* __restrict__ out) {
    __shared__ __align__(16) __half Yb[2][136 * YLD];
    __shared__ float Es[8][16 * 25];

    int tid = threadIdx.x, warp = tid >> 5, lane = tid & 31;
    int gq = lane >> 2, tig = lane & 3;
    int r = blockIdx.x;
    int br = blockIdx.y;
    int zz = blockIdx.z;
    int bb = zz >> 2, g = zz & 3;
    int c0 = warp * 16;

    const __half* xb = g_xh + ((size_t)bb * Hh + r) * Ww * 128 + g * 32;
    uint32_t a[2][4];
#pragma unroll
    for (int ks = 0; ks < 2; ks++) {
        a[ks][0] = *(const uint32_t*)(xb + (size_t)(c0 + gq) * 128 + ks * 16 + 2 * tig);
        a[ks][1] = *(const uint32_t*)(xb + (size_t)(c0 + gq + 8) * 128 + ks * 16 + 2 * tig);
        a[ks][2] = *(const uint32_t*)(xb + (size_t)(c0 + gq) * 128 + ks * 16 + 8 + 2 * tig);
        a[ks][3] = *(const uint32_t*)(xb + (size_t)(c0 + gq + 8) * 128 + ks * 16 + 8 + 2 * tig);
    }

    const __half* ysrc = g_ygh + (size_t)(br * NB + bb) * HP * WP * 128 + g * 32;
    {
        const __half* rowp = ysrc + (size_t)r * WP * 128;
        for (int i = tid; i < 544; i += 256) {
            int col = i >> 2, c = i & 3;
            cpa16(&Yb[0][col * YLD + c * 8], rowp + (size_t)col * 128 + c * 8);
        }
    }
    CP_COMMIT();

    const float* xnrow = g_xn + ((size_t)bb * 4 + g) * Hh * Ww + (size_t)r * Ww + c0;
    const float* ynb = g_yn + ((size_t)(br * NB + bb) * 4 + g) * HP * WP;
    size_t ob0 = ((size_t)(bb * 24 + br * 4 + g) * 81) * (Hh * Ww) + (size_t)r * Ww + c0;

    for (int sx = 0; sx < 9; sx++) {
        CP_WAIT0();
        __syncthreads();

        const uint32_t* sB = (const uint32_t*)Yb[sx & 1];
        uint32_t b0r[3][2], b1r[3][2];
#pragma unroll
        for (int nt = 0; nt < 3; nt++) {
            int col = c0 + nt * 8 + gq;
#pragma unroll
            for (int ks = 0; ks < 2; ks++) {
                b0r[nt][ks] = sB[col * 20 + tig + 8 * ks];
                b1r[nt][ks] = sB[col * 20 + tig + 4 + 8 * ks];
            }
        }
        if (sx < 8) {
            const __half* rowp = ysrc + (size_t)(r + sx + 1) * WP * 128;
            __half* db = Yb[(sx + 1) & 1];
            for (int i = tid; i < 544; i += 256) {
                int col = i >> 2, c = i & 3;
                cpa16(&db[col * YLD + c * 8], rowp + (size_t)col * 128 + c * 8);
            }
        }
        CP_COMMIT();

        float e[3][4];
#pragma unroll
        for (int nt = 0; nt < 3; nt++) {
            e[nt][0] = e[nt][1] = e[nt][2] = e[nt][3] = 0.f;
#pragma unroll
            for (int ks = 0; ks < 2; ks++)
                mma16(e[nt], a[ks], b0r[nt][ks], b1r[nt][ks]);
        }
        float* Ew = Es[warp];
#pragma unroll
        for (int nt = 0; nt < 3; nt++) {
            int cc = nt * 8 + 2 * tig;
            Ew[gq * 25 + cc] = e[nt][0];
            Ew[gq * 25 + cc + 1] = e[nt][1];
            Ew[(gq + 8) * 25 + cc] = e[nt][2];
            Ew[(gq + 8) * 25 + cc + 1] = e[nt][3];
        }
        __syncwarp();
        const float* ynrow = ynb + (size_t)(r + sx) * WP + c0;
        size_t ob = ob0 + (size_t)sx * 9 * (Hh * Ww);
#pragma unroll
        for (int u = 0; u < 3; u++) {
            int idx = lane + u * 32;
            if (idx < 72) {
                int sy = idx >> 3, pp = (idx & 7) * 2;
                float n0 = Ew[pp * 25 + pp + sy];
                float n1 = Ew[pp * 25 + pp + sy + 26];
                float d0 = fmaxf(xnrow[pp] * ynrow[pp + sy], 1e-8f);
                float d1 = fmaxf(xnrow[pp + 1] * ynrow[pp + 1 + sy], 1e-8f);
                *(float2*)&out[ob + (size_t)sy * (Hh * Ww) + pp] =
                    make_float2(__fdividef(n0, d0), __fdividef(n1, d1));
            }
        }
        __syncwarp();
    }
}

// ---------------- launch ----------------
extern "C" void kernel_launch(void* const* d_in, const int* in_sizes, int n_in,
                              void* d_out, int out_size) {
    const float* x    = (const float*)d_in[0];
    const float* y    = (const float*)d_in[1];
    const float* wts  = (const float*)d_in[2];
    const float* bias = (const float*)d_in[3];
    float* out = (float*)d_out;

    cudaFuncSetAttribute(conv_mma_kernel,
                         cudaFuncAttributeMaxDynamicSharedMemorySize, CONV_SMEM);

    pad_kernel<<<dim3(1, EXH, NB * 64), 192>>>(y);
    wt_kernel<<<(NBR * 9 * COUT * CIN + 255) / 256, 256>>>(wts);
    xn_kernel<<<dim3(48, NB * 4), 256>>>(x);
    conv_mma_kernel<<<dim3(104, 12), 256, CONV_SMEM>>>(bias);
    corr_kernel<<<dim3(Hh, NBR, NB * 4), 256>>>(out);
}

// round 15
// speedup vs baseline: 3.7808x; 3.7808x over previous
#include <cuda_runtime.h>
#include <cuda_fp16.h>
#include <math.h>
#include <cstdint>

#define Hh 96
#define Ww 128
#define HP 104
#define WP 136
#define CIN 128
#define COUT 128
#define NB 2
#define NBR 6
#define EXH 146            // HP + 2*21
#define EXW 178            // WP + 2*21
#define EXHW (EXH*EXW)

// -------- scratch (device globals: allocation-free) --------
__device__ __align__(16) __half g_ygh[(size_t)NBR * NB * HP * WP * 128];   // conv out [br][bb][row][col][ch]
__device__ __align__(16) float g_yn[(size_t)NBR * NB * 4 * HP * WP];
__device__ __align__(16) float g_xn[(size_t)NB * 4 * Hh * Ww];
__device__ __align__(16) __half g_xh[(size_t)NB * Hh * Ww * 128];          // x fp16 [bb][row][col][ch]
__device__ __align__(16) __half2 g_yext2[(size_t)NB * 64 * EXHW + 64];     // ci-pair fp16
__device__ __align__(16) __half g_wAh[(size_t)NBR * 9 * COUT * CIN];       // fp16 weights [br][tap][co][ci]

__constant__ int c_rad[6] = {1, 3, 5, 9, 13, 21};

__device__ __forceinline__ void mma16(float* c, const uint32_t* a, uint32_t b0, uint32_t b1) {
    asm volatile(
        "mma.sync.aligned.m16n8k16.row.col.f32.f16.f16.f32 "
        "{%0,%1,%2,%3}, {%4,%5,%6,%7}, {%8,%9}, {%0,%1,%2,%3};"
        : "+f"(c[0]), "+f"(c[1]), "+f"(c[2]), "+f"(c[3])
        : "r"(a[0]), "r"(a[1]), "r"(a[2]), "r"(a[3]), "r"(b0), "r"(b1));
}
__device__ __forceinline__ void ldsm_x4(uint32_t* r, uint32_t addr) {
    asm volatile("ldmatrix.sync.aligned.m8n8.x4.shared.b16 {%0,%1,%2,%3}, [%4];"
                 : "=r"(r[0]), "=r"(r[1]), "=r"(r[2]), "=r"(r[3]) : "r"(addr));
}
__device__ __forceinline__ void ldsm_x2(uint32_t* r, uint32_t addr) {
    asm volatile("ldmatrix.sync.aligned.m8n8.x2.shared.b16 {%0,%1}, [%2];"
                 : "=r"(r[0]), "=r"(r[1]) : "r"(addr));
}
__device__ __forceinline__ void cpa16(void* dst, const void* src) {
    uint32_t d = (uint32_t)__cvta_generic_to_shared(dst);
    asm volatile("cp.async.cg.shared.global [%0], [%1], 16;" :: "r"(d), "l"(src));
}
__device__ __forceinline__ void cpa4(void* dst, const void* src) {
    uint32_t d = (uint32_t)__cvta_generic_to_shared(dst);
    asm volatile("cp.async.ca.shared.global [%0], [%1], 4;" :: "r"(d), "l"(src));
}
#define CP_COMMIT() asm volatile("cp.async.commit_group;" ::: "memory")
#define CP_WAIT0()  asm volatile("cp.async.wait_group 0;" ::: "memory")

// ---------------- y_ext fp16 half2 (ci pairs): reflect pad + 21 zero halo ----------------
__global__ void pad_kernel(const float* __restrict__ y) {
    int c = threadIdx.x;
    if (c >= EXW) return;
    int rr = blockIdx.y;
    int cp = blockIdx.z & 63, bb = blockIdx.z >> 6;
    int pr = rr - 21, pc = c - 21;
    float v0 = 0.f, v1 = 0.f;
    if (pr >= 0 && pr < HP && pc >= 0 && pc < WP) {
        int yr = pr - 4; yr = yr < 0 ? -yr : yr; yr = yr >= Hh ? 2 * Hh - 2 - yr : yr;
        int yc = pc - 4; yc = yc < 0 ? -yc : yc; yc = yc >= Ww ? 2 * Ww - 2 - yc : yc;
        const float* p = y + ((size_t)bb * CIN + 2 * cp) * (Hh * Ww) + (size_t)yr * Ww + yc;
        v0 = p[0]; v1 = p[Hh * Ww];
    }
    g_yext2[((size_t)(bb * 64 + cp) * EXH + rr) * EXW + c] = __floats2half2_rn(v0, v1);
}

// ---------------- weight transform: wAh[br][tap][co][ci] fp16 ----------------
__global__ void wt_kernel(const float* __restrict__ w) {
    int idx = blockIdx.x * blockDim.x + threadIdx.x;
    if (idx >= NBR * 9 * COUT * CIN) return;
    int ci = idx % CIN; int t = idx / CIN;
    int co = t % COUT; t /= COUT;
    int tap = t % 9; int br = t / 9;
    g_wAh[idx] = __float2half_rn(w[(((size_t)br * COUT + co) * CIN + ci) * 9 + tap]);
}

// ---------------- xn + x fp16 transpose ----------------
__global__ void xn_kernel(const float* __restrict__ x) {
    int hw = blockIdx.x * 256 + threadIdx.x;
    int g = blockIdx.y & 3, bb = blockIdx.y >> 2;
    const float* xp = x + ((size_t)bb * CIN + g * 32) * (Hh * Ww) + hw;
    __half* xo = g_xh + ((size_t)bb * Hh * Ww + hw) * 128 + g * 32;
    float s = 0.f;
#pragma unroll
    for (int c = 0; c < 32; c++) {
        float v = xp[(size_t)c * Hh * Ww];
        s += v * v;
        xo[c] = __float2half_rn(v);
    }
    g_xn[((size_t)bb * 4 + g) * Hh * Ww + hw] = sqrtf(s);
}

// ---------------- fp16 mma.sync conv, K=64 per stage ----------------
#define LDA2 72
#define BCOL 36
#define A_HALFS 9216                 // 128*72
#define B_H2 6408                    // 178*36
#define OFF_B 36864                  // bytes: 2 A stages
#define CONV_SMEM (36864 + 2 * (B_H2 * 4))   // 88128 B

__device__ __forceinline__ void stage_A(__half* Abase, int it, int tid, const __half* wbr) {
    int qp = it / 9, tap = it % 9;
    const __half* wsrc = wbr + (size_t)tap * COUT * CIN + qp * 64;
#pragma unroll
    for (int i = tid; i < 1024; i += 256) {
        int co = i >> 3, k8 = i & 7;
        cpa16(Abase + co * LDA2 + k8 * 8, wsrc + (size_t)co * CIN + k8 * 8);
    }
}

__device__ __forceinline__ void stage_B(__half2* bt, int s, int piece, int tid,
                                        const __half2* yb2, int r, int d) {
    int qp = s / 3, kh = s % 3;
    int kr = tid >> 3, c0 = tid & 7;
    const __half2* rowp = yb2 + (size_t)(qp * 32 + kr) * EXHW
                        + (size_t)(r + 21 + d * (kh - 1)) * EXW;
    __half2* dst = bt + kr;
    if (piece < 2) {
        int jlo = piece * 8;
#pragma unroll
        for (int j = 0; j < 8; j++) {
            int c = c0 + 8 * (jlo + j);
            cpa4(dst + c * BCOL, rowp + c);
        }
    } else {
#pragma unroll
        for (int j = 16; j < 23; j++) {
            int c = c0 + 8 * j;
            if (c < EXW) cpa4(dst + c * BCOL, rowp + c);
        }
    }
}

__global__ __launch_bounds__(256, 2) void conv_mma_kernel(const float* __restrict__ bias) {
    extern __shared__ __align__(16) char dsm[];
    __half* Asm = (__half*)dsm;
    __half2* Bsm = (__half2*)(dsm + OFF_B);
    __half* ep = (__half*)dsm;     // epilogue reuse

    int tid = threadIdx.x, warp = tid >> 5, lane = tid & 31;
    int gq = lane >> 2, tig = lane & 3;
    int br = blockIdx.y >> 1, bb = blockIdx.y & 1;
    int r = blockIdx.x;
    int d = c_rad[br];
    int wm = warp & 3, wn = warp >> 2;
    int ntiles = wn ? 8 : 9;
    int tbase = wn * 9;

    const __half* wbr = g_wAh + (size_t)br * 9 * COUT * CIN;
    const __half2* yb2 = g_yext2 + (size_t)bb * 64 * EXHW;

    int aro = (lane & 15);
    int ako = (lane >> 4) << 3;
    int bco = (lane & 7) + ((lane >> 4) & 1) * 8;
    int bko = ((lane >> 3) & 1) * 4;

    float acc[2][9][4];
#pragma unroll
    for (int mt = 0; mt < 2; mt++)
#pragma unroll
        for (int t = 0; t < 9; t++)
#pragma unroll
            for (int u = 0; u < 4; u++) acc[mt][t][u] = 0.f;

    // prestage: full B stage 0 + A0, group 0
    stage_B(Bsm, 0, 0, tid, yb2, r, d);
    stage_B(Bsm, 0, 1, tid, yb2, r, d);
    stage_B(Bsm, 0, 2, tid, yb2, r, d);
    stage_A(Asm, 0, tid, wbr);
    CP_COMMIT();

    for (int it = 0; it < 18; ++it) {
        int s = it / 3, p = it % 3;
        int kw = p;
        CP_WAIT0();
        __syncthreads();

        uint32_t sAb = (uint32_t)__cvta_generic_to_shared(Asm + (it & 1) * A_HALFS);
        uint32_t sBb = (uint32_t)__cvta_generic_to_shared(Bsm + (s & 1) * B_H2);
        int off = 21 + d * (kw - 1);

        // STATIC-INDEX kk2 block (template param -> all acc/tp indices constant)
        auto kk2_block = [&](const int kk2) {
            uint32_t a0[4], a1[4];
            ldsm_x4(a0, sAb + ((wm * 32 + aro) * LDA2 + kk2 * 16 + ako) * 2);
            ldsm_x4(a1, sAb + ((wm * 32 + 16 + aro) * LDA2 + kk2 * 16 + ako) * 2);
#pragma unroll
            for (int tp = 0; tp < 4; tp++) {
                uint32_t b[4];
                int colb = off + (tbase + 2 * tp) * 8 + bco;
                ldsm_x4(b, sBb + (colb * BCOL + kk2 * 8 + bko) * 4);
                mma16(acc[0][2 * tp], a0, b[0], b[1]);
                mma16(acc[1][2 * tp], a1, b[0], b[1]);
                mma16(acc[0][2 * tp + 1], a0, b[2], b[3]);
                mma16(acc[1][2 * tp + 1], a1, b[2], b[3]);
            }
            if (ntiles == 9) {
                uint32_t b[2];
                int colb = off + (tbase + 8) * 8 + bco;
                ldsm_x2(b, sBb + (colb * BCOL + kk2 * 8 + bko) * 4);
                mma16(acc[0][8], a0, b[0], b[1]);
                mma16(acc[1][8], a1, b[0], b[1]);
            }
        };

        // warp-uniform branch stagger: wn=0 runs 0,1,2,3; wn=1 runs 2,3,0,1.
        if (wn == 0) {
            kk2_block(0);
            if (s + 1 < 6) stage_B(Bsm + ((s + 1) & 1) * B_H2, s + 1, p, tid, yb2, r, d);
            if (it + 1 < 18) stage_A(Asm + ((it + 1) & 1) * A_HALFS, it + 1, tid, wbr);
            CP_COMMIT();
            kk2_block(1);
            kk2_block(2);
            kk2_block(3);
        } else {
            kk2_block(2);
            if (s + 1 < 6) stage_B(Bsm + ((s + 1) & 1) * B_H2, s + 1, p, tid, yb2, r, d);
            if (it + 1 < 18) stage_A(Asm + ((it + 1) & 1) * A_HALFS, it + 1, tid, wbr);
            CP_COMMIT();
            kk2_block(3);
            kk2_block(0);
            kk2_block(1);
        }
    }
    CP_WAIT0();
    __syncthreads();

    // epilogue: bias + fp16 transpose -> g_ygh[row][col][ch]
#pragma unroll
    for (int mt = 0; mt < 2; mt++) {
        int co0 = wm * 32 + mt * 16 + gq, co1 = co0 + 8;
        float bv0 = bias[br * COUT + co0], bv1 = bias[br * COUT + co1];
#pragma unroll
        for (int t = 0; t < 9; t++) {
            if (t < ntiles) {
                int col = (tbase + t) * 8 + 2 * tig;
                ep[col * 128 + co0] = __float2half(acc[mt][t][0] + bv0);
                ep[(col + 1) * 128 + co0] = __float2half(acc[mt][t][1] + bv0);
                ep[col * 128 + co1] = __float2half(acc[mt][t][2] + bv1);
                ep[(col + 1) * 128 + co1] = __float2half(acc[mt][t][3] + bv1);
            }
        }
    }
    __syncthreads();
    __half* dst = g_ygh + ((size_t)(br * NB + bb) * HP + r) * WP * 128;
    const uint4* src = (const uint4*)ep;
    for (int i = tid; i < 136 * 128 / 8; i += 256)
        ((uint4*)dst)[i] = src[i];

    // fused yn
    for (int i = tid; i < 544; i += 256) {
        int col = i >> 2, g = i & 3;
        const __half2* pp = (const __half2*)(ep + col * 128 + g * 32);
        float s = 0.f;
#pragma unroll
        for (int k = 0; k < 16; k++) {
            int kk = (k + col) & 15;
            float2 f = __half22float2(pp[kk]);
            s += f.x * f.x + f.y * f.y;
        }
        g_yn[(((size_t)br * NB + bb) * 4 + g) * HP * WP + (size_t)r * WP + col] = sqrtf(s);
    }
}

// ---------------- tensor-core 81-shift correlation ----------------
#define YLD 40

__global__ __launch_bounds__(256, 3) void corr_kernel(float* __restrict__ out) {
    __shared__ __align__(16) __half Yb[2][136 * YLD];
    __shared__ float Es[8][16 * 25];

    int tid = threadIdx.x, warp = tid >> 5, lane = tid & 31;
    int gq = lane >> 2, tig = lane & 3;
    int r = blockIdx.x;
    int br = blockIdx.y;
    int zz = blockIdx.z;
    int bb = zz >> 2, g = zz & 3;
    int c0 = warp * 16;

    const __half* xb = g_xh + ((size_t)bb * Hh + r) * Ww * 128 + g * 32;
    uint32_t a[2][4];
#pragma unroll
    for (int ks = 0; ks < 2; ks++) {
        a[ks][0] = *(const uint32_t*)(xb + (size_t)(c0 + gq) * 128 + ks * 16 + 2 * tig);
        a[ks][1] = *(const uint32_t*)(xb + (size_t)(c0 + gq + 8) * 128 + ks * 16 + 2 * tig);
        a[ks][2] = *(const uint32_t*)(xb + (size_t)(c0 + gq) * 128 + ks * 16 + 8 + 2 * tig);
        a[ks][3] = *(const uint32_t*)(xb + (size_t)(c0 + gq + 8) * 128 + ks * 16 + 8 + 2 * tig);
    }

    const __half* ysrc = g_ygh + (size_t)(br * NB + bb) * HP * WP * 128 + g * 32;
    {
        const __half* rowp = ysrc + (size_t)r * WP * 128;
        for (int i = tid; i < 544; i += 256) {
            int col = i >> 2, c = i & 3;
            cpa16(&Yb[0][col * YLD + c * 8], rowp + (size_t)col * 128 + c * 8);
        }
    }
    CP_COMMIT();

    const float* xnrow = g_xn + ((size_t)bb * 4 + g) * Hh * Ww + (size_t)r * Ww + c0;
    const float* ynb = g_yn + ((size_t)(br * NB + bb) * 4 + g) * HP * WP;
    size_t ob0 = ((size_t)(bb * 24 + br * 4 + g) * 81) * (Hh * Ww) + (size_t)r * Ww + c0;

    for (int sx = 0; sx < 9; sx++) {
        CP_WAIT0();
        __syncthreads();

        const uint32_t* sB = (const uint32_t*)Yb[sx & 1];
        uint32_t b0r[3][2], b1r[3][2];
#pragma unroll
        for (int nt = 0; nt < 3; nt++) {
            int col = c0 + nt * 8 + gq;
#pragma unroll
            for (int ks = 0; ks < 2; ks++) {
                b0r[nt][ks] = sB[col * 20 + tig + 8 * ks];
                b1r[nt][ks] = sB[col * 20 + tig + 4 + 8 * ks];
            }
        }
        if (sx < 8) {
            const __half* rowp = ysrc + (size_t)(r + sx + 1) * WP * 128;
            __half* db = Yb[(sx + 1) & 1];
            for (int i = tid; i < 544; i += 256) {
                int col = i >> 2, c = i & 3;
                cpa16(&db[col * YLD + c * 8], rowp + (size_t)col * 128 + c * 8);
            }
        }
        CP_COMMIT();

        float e[3][4];
#pragma unroll
        for (int nt = 0; nt < 3; nt++) {
            e[nt][0] = e[nt][1] = e[nt][2] = e[nt][3] = 0.f;
#pragma unroll
            for (int ks = 0; ks < 2; ks++)
                mma16(e[nt], a[ks], b0r[nt][ks], b1r[nt][ks]);
        }
        float* Ew = Es[warp];
#pragma unroll
        for (int nt = 0; nt < 3; nt++) {
            int cc = nt * 8 + 2 * tig;
            Ew[gq * 25 + cc] = e[nt][0];
            Ew[gq * 25 + cc + 1] = e[nt][1];
            Ew[(gq + 8) * 25 + cc] = e[nt][2];
            Ew[(gq + 8) * 25 + cc + 1] = e[nt][3];
        }
        __syncwarp();
        const float* ynrow = ynb + (size_t)(r + sx) * WP + c0;
        size_t ob = ob0 + (size_t)sx * 9 * (Hh * Ww);
#pragma unroll
        for (int u = 0; u < 3; u++) {
            int idx = lane + u * 32;
            if (idx < 72) {
                int sy = idx >> 3, pp = (idx & 7) * 2;
                float n0 = Ew[pp * 25 + pp + sy];
                float n1 = Ew[pp * 25 + pp + sy + 26];
                float d0 = fmaxf(xnrow[pp] * ynrow[pp + sy], 1e-8f);
                float d1 = fmaxf(xnrow[pp + 1] * ynrow[pp + 1 + sy], 1e-8f);
                *(float2*)&out[ob + (size_t)sy * (Hh * Ww) + pp] =
                    make_float2(__fdividef(n0, d0), __fdividef(n1, d1));
            }
        }
        __syncwarp();
    }
}

// ---------------- launch ----------------
extern "C" void kernel_launch(void* const* d_in, const int* in_sizes, int n_in,
                              void* d_out, int out_size) {
    const float* x    = (const float*)d_in[0];
    const float* y    = (const float*)d_in[1];
    const float* wts  = (const float*)d_in[2];
    const float* bias = (const float*)d_in[3];
    float* out = (float*)d_out;

    cudaFuncSetAttribute(conv_mma_kernel,
                         cudaFuncAttributeMaxDynamicSharedMemorySize, CONV_SMEM);

    pad_kernel<<<dim3(1, EXH, NB * 64), 192>>>(y);
    wt_kernel<<<(NBR * 9 * COUT * CIN + 255) / 256, 256>>>(wts);
    xn_kernel<<<dim3(48, NB * 4), 256>>>(x);
    conv_mma_kernel<<<dim3(104, 12), 256, CONV_SMEM>>>(bias);
    corr_kernel<<<dim3(Hh, NBR, NB * 4), 256>>>(out);
}

// round 16
// speedup vs baseline: 3.8018x; 1.0056x over previous
#include <cuda_runtime.h>
#include <cuda_fp16.h>
#include <math.h>
#include <cstdint>

#define Hh 96
#define Ww 128
#define HP 104
#define WP 136
#define CIN 128
#define COUT 128
#define NB 2
#define NBR 6
#define EXH 146            // HP + 2*21
#define EXW 178            // WP + 2*21
#define EXHW (EXH*EXW)

// -------- scratch (device globals: allocation-free) --------
__device__ __align__(16) __half g_ygh[(size_t)NBR * NB * HP * WP * 128];   // conv out [br][bb][row][col][ch]
__device__ __align__(16) float g_yn[(size_t)NBR * NB * 4 * HP * WP];
__device__ __align__(16) float g_xn[(size_t)NB * 4 * Hh * Ww];
__device__ __align__(16) __half g_xh[(size_t)NB * Hh * Ww * 128];          // x fp16 [bb][row][col][ch]
__device__ __align__(16) __half2 g_yext2[(size_t)NB * 64 * EXHW + 64];     // ci-pair fp16
__device__ __align__(16) __half g_wAh[(size_t)NBR * 9 * COUT * CIN];       // fp16 weights [br][tap][co][ci]

__constant__ int c_rad[6] = {1, 3, 5, 9, 13, 21};

__device__ __forceinline__ void mma16(float* c, const uint32_t* a, uint32_t b0, uint32_t b1) {
    asm volatile(
        "mma.sync.aligned.m16n8k16.row.col.f32.f16.f16.f32 "
        "{%0,%1,%2,%3}, {%4,%5,%6,%7}, {%8,%9}, {%0,%1,%2,%3};"
        : "+f"(c[0]), "+f"(c[1]), "+f"(c[2]), "+f"(c[3])
        : "r"(a[0]), "r"(a[1]), "r"(a[2]), "r"(a[3]), "r"(b0), "r"(b1));
}
__device__ __forceinline__ void ldsm_x4(uint32_t* r, uint32_t addr) {
    asm volatile("ldmatrix.sync.aligned.m8n8.x4.shared.b16 {%0,%1,%2,%3}, [%4];"
                 : "=r"(r[0]), "=r"(r[1]), "=r"(r[2]), "=r"(r[3]) : "r"(addr));
}
__device__ __forceinline__ void ldsm_x2(uint32_t* r, uint32_t addr) {
    asm volatile("ldmatrix.sync.aligned.m8n8.x2.shared.b16 {%0,%1}, [%2];"
                 : "=r"(r[0]), "=r"(r[1]) : "r"(addr));
}
__device__ __forceinline__ void cpa16(void* dst, const void* src) {
    uint32_t d = (uint32_t)__cvta_generic_to_shared(dst);
    asm volatile("cp.async.cg.shared.global [%0], [%1], 16;" :: "r"(d), "l"(src));
}
__device__ __forceinline__ void cpa4(void* dst, const void* src) {
    uint32_t d = (uint32_t)__cvta_generic_to_shared(dst);
    asm volatile("cp.async.ca.shared.global [%0], [%1], 4;" :: "r"(d), "l"(src));
}
#define CP_COMMIT() asm volatile("cp.async.commit_group;" ::: "memory")
#define CP_WAIT0()  asm volatile("cp.async.wait_group 0;" ::: "memory")

// ---------------- y_ext fp16 half2 (ci pairs): reflect pad + 21 zero halo ----------------
__global__ void pad_kernel(const float* __restrict__ y) {
    int c = threadIdx.x;
    if (c >= EXW) return;
    int rr = blockIdx.y;
    int cp = blockIdx.z & 63, bb = blockIdx.z >> 6;
    int pr = rr - 21, pc = c - 21;
    float v0 = 0.f, v1 = 0.f;
    if (pr >= 0 && pr < HP && pc >= 0 && pc < WP) {
        int yr = pr - 4; yr = yr < 0 ? -yr : yr; yr = yr >= Hh ? 2 * Hh - 2 - yr : yr;
        int yc = pc - 4; yc = yc < 0 ? -yc : yc; yc = yc >= Ww ? 2 * Ww - 2 - yc : yc;
        const float* p = y + ((size_t)bb * CIN + 2 * cp) * (Hh * Ww) + (size_t)yr * Ww + yc;
        v0 = p[0]; v1 = p[Hh * Ww];
    }
    g_yext2[((size_t)(bb * 64 + cp) * EXH + rr) * EXW + c] = __floats2half2_rn(v0, v1);
}

// ---------------- weight transform: wAh[br][tap][co][ci] fp16 ----------------
__global__ void wt_kernel(const float* __restrict__ w) {
    int idx = blockIdx.x * blockDim.x + threadIdx.x;
    if (idx >= NBR * 9 * COUT * CIN) return;
    int ci = idx % CIN; int t = idx / CIN;
    int co = t % COUT; t /= COUT;
    int tap = t % 9; int br = t / 9;
    g_wAh[idx] = __float2half_rn(w[(((size_t)br * COUT + co) * CIN + ci) * 9 + tap]);
}

// ---------------- xn + x fp16 transpose ----------------
__global__ void xn_kernel(const float* __restrict__ x) {
    int hw = blockIdx.x * 256 + threadIdx.x;
    int g = blockIdx.y & 3, bb = blockIdx.y >> 2;
    const float* xp = x + ((size_t)bb * CIN + g * 32) * (Hh * Ww) + hw;
    __half* xo = g_xh + ((size_t)bb * Hh * Ww + hw) * 128 + g * 32;
    float s = 0.f;
#pragma unroll
    for (int c = 0; c < 32; c++) {
        float v = xp[(size_t)c * Hh * Ww];
        s += v * v;
        xo[c] = __float2half_rn(v);
    }
    g_xn[((size_t)bb * 4 + g) * Hh * Ww + hw] = sqrtf(s);
}

// ---------------- fp16 mma.sync conv, K=64 per stage (unchanged from R15) ----------------
#define LDA2 72
#define BCOL 36
#define A_HALFS 9216
#define B_H2 6408
#define OFF_B 36864
#define CONV_SMEM (36864 + 2 * (B_H2 * 4))   // 88128 B

__device__ __forceinline__ void stage_A(__half* Abase, int it, int tid, const __half* wbr) {
    int qp = it / 9, tap = it % 9;
    const __half* wsrc = wbr + (size_t)tap * COUT * CIN + qp * 64;
#pragma unroll
    for (int i = tid; i < 1024; i += 256) {
        int co = i >> 3, k8 = i & 7;
        cpa16(Abase + co * LDA2 + k8 * 8, wsrc + (size_t)co * CIN + k8 * 8);
    }
}

__device__ __forceinline__ void stage_B(__half2* bt, int s, int piece, int tid,
                                        const __half2* yb2, int r, int d) {
    int qp = s / 3, kh = s % 3;
    int kr = tid >> 3, c0 = tid & 7;
    const __half2* rowp = yb2 + (size_t)(qp * 32 + kr) * EXHW
                        + (size_t)(r + 21 + d * (kh - 1)) * EXW;
    __half2* dst = bt + kr;
    if (piece < 2) {
        int jlo = piece * 8;
#pragma unroll
        for (int j = 0; j < 8; j++) {
            int c = c0 + 8 * (jlo + j);
            cpa4(dst + c * BCOL, rowp + c);
        }
    } else {
#pragma unroll
        for (int j = 16; j < 23; j++) {
            int c = c0 + 8 * j;
            if (c < EXW) cpa4(dst + c * BCOL, rowp + c);
        }
    }
}

__global__ __launch_bounds__(256, 2) void conv_mma_kernel(const float* __restrict__ bias) {
    extern __shared__ __align__(16) char dsm[];
    __half* Asm = (__half*)dsm;
    __half2* Bsm = (__half2*)(dsm + OFF_B);
    __half* ep = (__half*)dsm;

    int tid = threadIdx.x, warp = tid >> 5, lane = tid & 31;
    int gq = lane >> 2, tig = lane & 3;
    int br = blockIdx.y >> 1, bb = blockIdx.y & 1;
    int r = blockIdx.x;
    int d = c_rad[br];
    int wm = warp & 3, wn = warp >> 2;
    int ntiles = wn ? 8 : 9;
    int tbase = wn * 9;

    const __half* wbr = g_wAh + (size_t)br * 9 * COUT * CIN;
    const __half2* yb2 = g_yext2 + (size_t)bb * 64 * EXHW;

    int aro = (lane & 15);
    int ako = (lane >> 4) << 3;
    int bco = (lane & 7) + ((lane >> 4) & 1) * 8;
    int bko = ((lane >> 3) & 1) * 4;

    float acc[2][9][4];
#pragma unroll
    for (int mt = 0; mt < 2; mt++)
#pragma unroll
        for (int t = 0; t < 9; t++)
#pragma unroll
            for (int u = 0; u < 4; u++) acc[mt][t][u] = 0.f;

    stage_B(Bsm, 0, 0, tid, yb2, r, d);
    stage_B(Bsm, 0, 1, tid, yb2, r, d);
    stage_B(Bsm, 0, 2, tid, yb2, r, d);
    stage_A(Asm, 0, tid, wbr);
    CP_COMMIT();

    for (int it = 0; it < 18; ++it) {
        int s = it / 3, p = it % 3;
        int kw = p;
        CP_WAIT0();
        __syncthreads();

        uint32_t sAb = (uint32_t)__cvta_generic_to_shared(Asm + (it & 1) * A_HALFS);
        uint32_t sBb = (uint32_t)__cvta_generic_to_shared(Bsm + (s & 1) * B_H2);
        int off = 21 + d * (kw - 1);

        auto kk2_block = [&](const int kk2) {
            uint32_t a0[4], a1[4];
            ldsm_x4(a0, sAb + ((wm * 32 + aro) * LDA2 + kk2 * 16 + ako) * 2);
            ldsm_x4(a1, sAb + ((wm * 32 + 16 + aro) * LDA2 + kk2 * 16 + ako) * 2);
#pragma unroll
            for (int tp = 0; tp < 4; tp++) {
                uint32_t b[4];
                int colb = off + (tbase + 2 * tp) * 8 + bco;
                ldsm_x4(b, sBb + (colb * BCOL + kk2 * 8 + bko) * 4);
                mma16(acc[0][2 * tp], a0, b[0], b[1]);
                mma16(acc[1][2 * tp], a1, b[0], b[1]);
                mma16(acc[0][2 * tp + 1], a0, b[2], b[3]);
                mma16(acc[1][2 * tp + 1], a1, b[2], b[3]);
            }
            if (ntiles == 9) {
                uint32_t b[2];
                int colb = off + (tbase + 8) * 8 + bco;
                ldsm_x2(b, sBb + (colb * BCOL + kk2 * 8 + bko) * 4);
                mma16(acc[0][8], a0, b[0], b[1]);
                mma16(acc[1][8], a1, b[0], b[1]);
            }
        };

        if (wn == 0) {
            kk2_block(0);
            if (s + 1 < 6) stage_B(Bsm + ((s + 1) & 1) * B_H2, s + 1, p, tid, yb2, r, d);
            if (it + 1 < 18) stage_A(Asm + ((it + 1) & 1) * A_HALFS, it + 1, tid, wbr);
            CP_COMMIT();
            kk2_block(1);
            kk2_block(2);
            kk2_block(3);
        } else {
            kk2_block(2);
            if (s + 1 < 6) stage_B(Bsm + ((s + 1) & 1) * B_H2, s + 1, p, tid, yb2, r, d);
            if (it + 1 < 18) stage_A(Asm + ((it + 1) & 1) * A_HALFS, it + 1, tid, wbr);
            CP_COMMIT();
            kk2_block(3);
            kk2_block(0);
            kk2_block(1);
        }
    }
    CP_WAIT0();
    __syncthreads();

#pragma unroll
    for (int mt = 0; mt < 2; mt++) {
        int co0 = wm * 32 + mt * 16 + gq, co1 = co0 + 8;
        float bv0 = bias[br * COUT + co0], bv1 = bias[br * COUT + co1];
#pragma unroll
        for (int t = 0; t < 9; t++) {
            if (t < ntiles) {
                int col = (tbase + t) * 8 + 2 * tig;
                ep[col * 128 + co0] = __float2half(acc[mt][t][0] + bv0);
                ep[(col + 1) * 128 + co0] = __float2half(acc[mt][t][1] + bv0);
                ep[col * 128 + co1] = __float2half(acc[mt][t][2] + bv1);
                ep[(col + 1) * 128 + co1] = __float2half(acc[mt][t][3] + bv1);
            }
        }
    }
    __syncthreads();
    __half* dst = g_ygh + ((size_t)(br * NB + bb) * HP + r) * WP * 128;
    const uint4* src = (const uint4*)ep;
    for (int i = tid; i < 136 * 128 / 8; i += 256)
        ((uint4*)dst)[i] = src[i];

    for (int i = tid; i < 544; i += 256) {
        int col = i >> 2, g = i & 3;
        const __half2* pp = (const __half2*)(ep + col * 128 + g * 32);
        float s = 0.f;
#pragma unroll
        for (int k = 0; k < 16; k++) {
            int kk = (k + col) & 15;
            float2 f = __half22float2(pp[kk]);
            s += f.x * f.x + f.y * f.y;
        }
        g_yn[(((size_t)br * NB + bb) * 4 + g) * HP * WP + (size_t)r * WP + col] = sqrtf(s);
    }
}

// ---------------- tensor-core 81-shift correlation, 8 rows/CTA + 9-slot ring ----------------
#define YLD 40                      // halfs per col slot (16B-aligned stride)
#define SLOT_H 5440                 // halfs per ring slot (136*40)
#define RING_BYTES (9 * SLOT_H * 2) // 97920
#define CORR_SMEM (RING_BYTES + 8 * 400 * 4)   // + Es: 110720 B

__global__ __launch_bounds__(256, 2) void corr_kernel(float* __restrict__ out) {
    extern __shared__ __align__(16) char csm[];
    __half* ring = (__half*)csm;
    float* Esb = (float*)(csm + RING_BYTES);

    int tid = threadIdx.x, warp = tid >> 5, lane = tid & 31;
    int gq = lane >> 2, tig = lane & 3;
    int r0 = blockIdx.x * 8;
    int br = blockIdx.y;
    int zz = blockIdx.z;
    int bb = zz >> 2, g = zz & 3;
    int c0 = warp * 16;
    float* Ew = Esb + warp * 400;

    const __half* ysrc = g_ygh + (size_t)(br * NB + bb) * HP * WP * 128 + g * 32;

    // initial stage: rows r0..r0+8 -> slots 0..8 (one group)
#pragma unroll
    for (int s = 0; s < 9; s++) {
        const __half* rowp = ysrc + (size_t)(r0 + s) * WP * 128;
        __half* slot = ring + s * SLOT_H;
        for (int i = tid; i < 544; i += 256) {
            int col = i >> 2, c = i & 3;
            cpa16(slot + col * YLD + c * 8, rowp + (size_t)col * 128 + c * 8);
        }
    }
    CP_COMMIT();

    const float* xnb = g_xn + ((size_t)bb * 4 + g) * Hh * Ww;
    const float* ynb = g_yn + ((size_t)(br * NB + bb) * 4 + g) * HP * WP;
    size_t obase = ((size_t)(bb * 24 + br * 4 + g) * 81) * (Hh * Ww);

    for (int j = 0; j < 8; j++) {
        CP_WAIT0();
        __syncthreads();
        int r = r0 + j;

        // A fragments for this output row
        const __half* xb = g_xh + ((size_t)bb * Hh + r) * Ww * 128 + g * 32;
        uint32_t a[2][4];
#pragma unroll
        for (int ks = 0; ks < 2; ks++) {
            a[ks][0] = *(const uint32_t*)(xb + (size_t)(c0 + gq) * 128 + ks * 16 + 2 * tig);
            a[ks][1] = *(const uint32_t*)(xb + (size_t)(c0 + gq + 8) * 128 + ks * 16 + 2 * tig);
            a[ks][2] = *(const uint32_t*)(xb + (size_t)(c0 + gq) * 128 + ks * 16 + 8 + 2 * tig);
            a[ks][3] = *(const uint32_t*)(xb + (size_t)(c0 + gq + 8) * 128 + ks * 16 + 8 + 2 * tig);
        }
        const float* xnrow = xnb + (size_t)r * Ww + c0;
        size_t ob0 = obase + (size_t)r * Ww + c0;

        auto do_sx = [&](int sx) {
            int slot = j + sx; if (slot >= 9) slot -= 9;
            const uint32_t* sB = (const uint32_t*)(ring + slot * SLOT_H);
            uint32_t b0r[3][2], b1r[3][2];
#pragma unroll
            for (int nt = 0; nt < 3; nt++) {
                int col = c0 + nt * 8 + gq;
#pragma unroll
                for (int ks = 0; ks < 2; ks++) {
                    b0r[nt][ks] = sB[col * 20 + tig + 8 * ks];
                    b1r[nt][ks] = sB[col * 20 + tig + 4 + 8 * ks];
                }
            }
            float e[3][4];
#pragma unroll
            for (int nt = 0; nt < 3; nt++) {
                e[nt][0] = e[nt][1] = e[nt][2] = e[nt][3] = 0.f;
#pragma unroll
                for (int ks = 0; ks < 2; ks++)
                    mma16(e[nt], a[ks], b0r[nt][ks], b1r[nt][ks]);
            }
#pragma unroll
            for (int nt = 0; nt < 3; nt++) {
                int cc = nt * 8 + 2 * tig;
                Ew[gq * 25 + cc] = e[nt][0];
                Ew[gq * 25 + cc + 1] = e[nt][1];
                Ew[(gq + 8) * 25 + cc] = e[nt][2];
                Ew[(gq + 8) * 25 + cc + 1] = e[nt][3];
            }
            __syncwarp();
            const float* ynrow = ynb + (size_t)(r + sx) * WP + c0;
            size_t ob = ob0 + (size_t)sx * 9 * (Hh * Ww);
#pragma unroll
            for (int u = 0; u < 3; u++) {
                int idx = lane + u * 32;
                if (idx < 72) {
                    int sy = idx >> 3, pp = (idx & 7) * 2;
                    float n0 = Ew[pp * 25 + pp + sy];
                    float n1 = Ew[pp * 25 + pp + sy + 26];
                    float d0 = fmaxf(xnrow[pp] * ynrow[pp + sy], 1e-8f);
                    float d1 = fmaxf(xnrow[pp + 1] * ynrow[pp + 1 + sy], 1e-8f);
                    *(float2*)&out[ob + (size_t)sy * (Hh * Ww) + pp] =
                        make_float2(__fdividef(n0, d0), __fdividef(n1, d1));
                }
            }
            __syncwarp();
        };

        do_sx(0);
        __syncthreads();      // all warps done with row j's slot
        if (j < 7) {          // prefetch row r0+j+9 into the freed slot (j%9 == j)
            const __half* rowp = ysrc + (size_t)(r0 + j + 9) * WP * 128;
            __half* slot = ring + j * SLOT_H;
            for (int i = tid; i < 544; i += 256) {
                int col = i >> 2, c = i & 3;
                cpa16(slot + col * YLD + c * 8, rowp + (size_t)col * 128 + c * 8);
            }
        }
        CP_COMMIT();
#pragma unroll
        for (int sx = 1; sx < 9; sx++) do_sx(sx);
    }
}

// ---------------- launch ----------------
extern "C" void kernel_launch(void* const* d_in, const int* in_sizes, int n_in,
                              void* d_out, int out_size) {
    const float* x    = (const float*)d_in[0];
    const float* y    = (const float*)d_in[1];
    const float* wts  = (const float*)d_in[2];
    const float* bias = (const float*)d_in[3];
    float* out = (float*)d_out;

    cudaFuncSetAttribute(conv_mma_kernel,
                         cudaFuncAttributeMaxDynamicSharedMemorySize, CONV_SMEM);
    cudaFuncSetAttribute(corr_kernel,
                         cudaFuncAttributeMaxDynamicSharedMemorySize, CORR_SMEM);

    pad_kernel<<<dim3(1, EXH, NB * 64), 192>>>(y);
    wt_kernel<<<(NBR * 9 * COUT * CIN + 255) / 256, 256>>>(wts);
    xn_kernel<<<dim3(48, NB * 4), 256>>>(x);
    conv_mma_kernel<<<dim3(104, 12), 256, CONV_SMEM>>>(bias);
    corr_kernel<<<dim3(12, NBR, NB * 4), 256, CORR_SMEM>>>(out);
}